// round 2
// baseline (speedup 1.0000x reference)
#include <cuda_runtime.h>
#include <cuda_bf16.h>
#include <stdint.h>

#define N_NODES 50000
#define N_EDGES 800000

// ---------------- scratch (device globals; no allocation allowed) ----------
__device__ int   g_is64;                 // 1 if edge_index stored as int64
__device__ int   g_deg[N_NODES];
__device__ int   g_rowptr[N_NODES + 1];
__device__ int   g_rowcur[N_NODES];
__device__ int   g_colidx[N_EDGES];
__device__ int   g_bsum[64];
__device__ float g_dis[N_NODES];
__device__ float g_feat[N_NODES * 64];   // scaled features g = dis*h (agg input)
__device__ float g_agg [N_NODES * 64];   // aggregated features (gemm input)
__device__ float g_actA[N_NODES * 128];  // dense-layer ping
__device__ float g_actB[N_NODES * 128];  // dense-layer pong

// ---------------- edge-index dtype probe ------------------------------------
__global__ void k_detect(const void* __restrict__ ei) {
    if (threadIdx.x == 0 && blockIdx.x == 0) {
        const long long* p = (const long long*)ei;
        int ok64 = 1;
        for (int i = 0; i < 64; i++) {
            long long v = p[i];
            if (v < 0 || v >= N_NODES) { ok64 = 0; break; }
        }
        g_is64 = ok64;
    }
}

__device__ __forceinline__ int edge_at(const void* ei, long long idx) {
    if (g_is64) return (int)((const long long*)ei)[idx];
    return ((const int*)ei)[idx];
}

// ---------------- CSR build -------------------------------------------------
__global__ void k_zero_deg() {
    int i = blockIdx.x * blockDim.x + threadIdx.x;
    if (i < N_NODES) g_deg[i] = 0;
}

__global__ void k_hist(const void* __restrict__ ei) {
    int e = blockIdx.x * blockDim.x + threadIdx.x;
    if (e < N_EDGES) {
        int d = edge_at(ei, (long long)N_EDGES + e);   // row 1 = dst
        if (d >= 0 && d < N_NODES) atomicAdd(&g_deg[d], 1);
    }
}

// block-level exclusive scan (1024 per block)
__global__ void k_scan1() {
    __shared__ int s[1024];
    int i = blockIdx.x * 1024 + threadIdx.x;
    int v = (i < N_NODES) ? g_deg[i] : 0;
    s[threadIdx.x] = v;
    __syncthreads();
    for (int off = 1; off < 1024; off <<= 1) {
        int t = (threadIdx.x >= off) ? s[threadIdx.x - off] : 0;
        __syncthreads();
        s[threadIdx.x] += t;
        __syncthreads();
    }
    if (i < N_NODES) g_rowptr[i] = s[threadIdx.x] - v;  // exclusive
    if (threadIdx.x == 1023) g_bsum[blockIdx.x] = s[1023];
}

__global__ void k_scan2(int nb) {
    __shared__ int s[64];
    int v = (threadIdx.x < nb) ? g_bsum[threadIdx.x] : 0;
    s[threadIdx.x] = v;
    __syncthreads();
    for (int off = 1; off < 64; off <<= 1) {
        int t = (threadIdx.x >= off) ? s[threadIdx.x - off] : 0;
        __syncthreads();
        s[threadIdx.x] += t;
        __syncthreads();
    }
    if (threadIdx.x < nb) g_bsum[threadIdx.x] = s[threadIdx.x] - v;  // exclusive
}

__global__ void k_scan3() {
    int i = blockIdx.x * blockDim.x + threadIdx.x;
    if (i < N_NODES) {
        int r = g_rowptr[i] + g_bsum[i >> 10];
        g_rowptr[i] = r;
        g_rowcur[i] = r;
        g_dis[i]    = rsqrtf((float)(g_deg[i] + 1));  // +1 self-loop
    }
    if (i == 0) g_rowptr[N_NODES] = N_EDGES;
}

__global__ void k_scatter(const void* __restrict__ ei) {
    int e = blockIdx.x * blockDim.x + threadIdx.x;
    if (e < N_EDGES) {
        int s = edge_at(ei, e);                          // row 0 = src
        int d = edge_at(ei, (long long)N_EDGES + e);     // row 1 = dst
        if (d >= 0 && d < N_NODES && s >= 0 && s < N_NODES) {
            int p = atomicAdd(&g_rowcur[d], 1);
            g_colidx[p] = s;
        }
    }
}

// ---------------- feature scaling for layer-1 input ------------------------
__global__ void k_scale16(const float* __restrict__ x) {
    int idx = blockIdx.x * blockDim.x + threadIdx.x;
    if (idx < N_NODES * 16) {
        int node = idx >> 4;
        g_feat[idx] = x[idx] * g_dis[node];
    }
}

// ---------------- aggregation: one warp per node ---------------------------
// agg[d] = dis[d] * ( g[d] + sum_{e: dst=d} g[src[e]] )
template <int D>
__global__ void k_agg(const float* __restrict__ g, float* __restrict__ agg) {
    constexpr int COLS = (D + 31) / 32;
    int warp = (blockIdx.x * blockDim.x + threadIdx.x) >> 5;
    if (warp >= N_NODES) return;
    int lane = threadIdx.x & 31;

    float acc[COLS];
#pragma unroll
    for (int c = 0; c < COLS; c++) {
        int col = lane + 32 * c;
        acc[c] = (col < D) ? __ldg(&g[(size_t)warp * D + col]) : 0.f;  // self loop
    }

    int beg = g_rowptr[warp];
    int end = g_rowptr[warp + 1];
    int p = beg;
    for (; p + 4 <= end; p += 4) {
        int s0 = g_colidx[p + 0];
        int s1 = g_colidx[p + 1];
        int s2 = g_colidx[p + 2];
        int s3 = g_colidx[p + 3];
#pragma unroll
        for (int c = 0; c < COLS; c++) {
            int col = lane + 32 * c;
            if (col < D) {
                acc[c] += __ldg(&g[(size_t)s0 * D + col]);
                acc[c] += __ldg(&g[(size_t)s1 * D + col]);
                acc[c] += __ldg(&g[(size_t)s2 * D + col]);
                acc[c] += __ldg(&g[(size_t)s3 * D + col]);
            }
        }
    }
    for (; p < end; p++) {
        int s = g_colidx[p];
#pragma unroll
        for (int c = 0; c < COLS; c++) {
            int col = lane + 32 * c;
            if (col < D) acc[c] += __ldg(&g[(size_t)s * D + col]);
        }
    }

    float dd = g_dis[warp];
#pragma unroll
    for (int c = 0; c < COLS; c++) {
        int col = lane + 32 * c;
        if (col < D) agg[(size_t)warp * D + col] = acc[c] * dd;
    }
}

// ---------------- GEMM + bias + relu (+ optional dis-scale fused) ----------
// out[n, :] = relu(in[n, :] @ W + b) * (SCALE ? dis[n] : 1)
template <int DIN, int DOUT, bool SCALE>
__global__ void k_gemm(const float* __restrict__ in,
                       const float* __restrict__ W,
                       const float* __restrict__ b,
                       float* __restrict__ out) {
    constexpr int CH     = (DOUT < 32) ? DOUT : 32;
    constexpr int CHUNKS = DOUT / CH;

    __shared__ float Ws[DIN * DOUT];
    __shared__ float bs[DOUT];
    for (int i = threadIdx.x; i < DIN * DOUT; i += blockDim.x) Ws[i] = W[i];
    for (int i = threadIdx.x; i < DOUT; i += blockDim.x) bs[i] = b[i];
    __syncthreads();

    int t    = blockIdx.x * blockDim.x + threadIdx.x;
    int node = t / CHUNKS;
    int ch   = t % CHUNKS;
    if (node >= N_NODES) return;

    float acc[CH];
#pragma unroll
    for (int j = 0; j < CH; j++) acc[j] = bs[ch * CH + j];

    const float* row = in + (size_t)node * DIN;
#pragma unroll 4
    for (int k = 0; k < DIN; k++) {
        float a = __ldg(&row[k]);
#pragma unroll
        for (int j = 0; j < CH; j++)
            acc[j] = fmaf(a, Ws[k * DOUT + ch * CH + j], acc[j]);
    }

    float sc = 1.f;
    if (SCALE) sc = g_dis[node];
    float* o = out + (size_t)node * DOUT + ch * CH;
#pragma unroll
    for (int j = 0; j < CH; j++) {
        float v = acc[j];
        v = v > 0.f ? v : 0.f;
        o[j] = v * sc;
    }
}

// ---------------- launch ----------------------------------------------------
extern "C" void kernel_launch(void* const* d_in, const int* in_sizes, int n_in,
                              void* d_out, int out_size) {
    const float* x  = (const float*)d_in[0];
    const void*  ei = d_in[1];
    const float *W1 = (const float*)d_in[2],  *b1 = (const float*)d_in[3];
    const float *W2 = (const float*)d_in[4],  *b2 = (const float*)d_in[5];
    const float *W3 = (const float*)d_in[6],  *b3 = (const float*)d_in[7];
    const float *Wl1= (const float*)d_in[8],  *bl1= (const float*)d_in[9];
    const float *Wl2= (const float*)d_in[10], *bl2= (const float*)d_in[11];
    const float *Wl3= (const float*)d_in[12], *bl3= (const float*)d_in[13];
    float* out = (float*)d_out;

    float *feat, *agg, *actA, *actB;
    cudaGetSymbolAddress((void**)&feat, g_feat);
    cudaGetSymbolAddress((void**)&agg,  g_agg);
    cudaGetSymbolAddress((void**)&actA, g_actA);
    cudaGetSymbolAddress((void**)&actB, g_actB);

    const int TB = 256;
    const int nodeBlocks = (N_NODES + TB - 1) / TB;
    const int edgeBlocks = (N_EDGES + TB - 1) / TB;
    const int scanBlocks = (N_NODES + 1023) / 1024;
    const int aggBlocks  = (N_NODES * 32 + TB - 1) / TB;

    // --- graph structure (once per launch) ---
    k_detect<<<1, 32>>>(ei);
    k_zero_deg<<<nodeBlocks, TB>>>();
    k_hist<<<edgeBlocks, TB>>>(ei);
    k_scan1<<<scanBlocks, 1024>>>();
    k_scan2<<<1, 64>>>(scanBlocks);
    k_scan3<<<nodeBlocks, TB>>>();
    k_scatter<<<edgeBlocks, TB>>>(ei);

    // --- conv 1: d 16 -> 32 ---
    k_scale16<<<(N_NODES * 16 + TB - 1) / TB, TB>>>(x);
    k_agg<16><<<aggBlocks, TB>>>(feat, agg);
    k_gemm<16, 32, true><<<(N_NODES * 1 + TB - 1) / TB, TB>>>(agg, W1, b1, feat);

    // --- conv 2: d 32 -> 64 ---
    k_agg<32><<<aggBlocks, TB>>>(feat, agg);
    k_gemm<32, 64, true><<<(N_NODES * 2 + TB - 1) / TB, TB>>>(agg, W2, b2, feat);

    // --- conv 3: d 64 -> 128 ---
    k_agg<64><<<aggBlocks, TB>>>(feat, agg);
    k_gemm<64, 128, false><<<(N_NODES * 4 + TB - 1) / TB, TB>>>(agg, W3, b3, actA);

    // --- dense layers ---
    k_gemm<128, 64, false><<<(N_NODES * 2 + TB - 1) / TB, TB>>>(actA, Wl1, bl1, actB);
    k_gemm<64, 32, false><<<(N_NODES * 1 + TB - 1) / TB, TB>>>(actB, Wl2, bl2, actA);
    k_gemm<32, 16, false><<<(N_NODES * 1 + TB - 1) / TB, TB>>>(actA, Wl3, bl3, out);
}

// round 3
// speedup vs baseline: 2.6314x; 2.6314x over previous
#include <cuda_runtime.h>
#include <cuda_bf16.h>
#include <stdint.h>

#define N_NODES 50000
#define N_EDGES 800000

// ---------------- scratch (device globals; no allocation allowed) ----------
__device__ int   g_is64;
__device__ int   g_deg[N_NODES];
__device__ int   g_rowptr[N_NODES + 1];
__device__ int   g_rowcur[N_NODES];
__device__ int   g_colidx[N_EDGES];
__device__ int   g_bsum[64];
__device__ float g_dis[N_NODES];
__device__ float g_feat[N_NODES * 64];
__device__ float g_agg [N_NODES * 64];
__device__ float g_actA[N_NODES * 128];
__device__ float g_actB[N_NODES * 128];

// ---------------- packed f32x2 helpers (Blackwell) ---------------------------
__device__ __forceinline__ unsigned long long pack2(float x, float y) {
    unsigned long long r;
    asm("mov.b64 %0, {%1, %2};" : "=l"(r) : "f"(x), "f"(y));
    return r;
}
__device__ __forceinline__ void unpack2(unsigned long long v, float& x, float& y) {
    asm("mov.b64 {%0, %1}, %2;" : "=f"(x), "=f"(y) : "l"(v));
}
__device__ __forceinline__ unsigned long long fma2(unsigned long long a,
                                                   unsigned long long b,
                                                   unsigned long long c) {
    unsigned long long d;
    asm("fma.rn.f32x2 %0, %1, %2, %3;" : "=l"(d) : "l"(a), "l"(b), "l"(c));
    return d;
}

// ---------------- edge-index dtype probe ------------------------------------
__global__ void k_detect(const void* __restrict__ ei) {
    if (threadIdx.x == 0 && blockIdx.x == 0) {
        const long long* p = (const long long*)ei;
        int ok64 = 1;
        for (int i = 0; i < 64; i++) {
            long long v = p[i];
            if (v < 0 || v >= N_NODES) { ok64 = 0; break; }
        }
        g_is64 = ok64;
    }
}

__device__ __forceinline__ int edge_at(const void* ei, long long idx) {
    if (g_is64) return (int)((const long long*)ei)[idx];
    return ((const int*)ei)[idx];
}

// ---------------- CSR build -------------------------------------------------
__global__ void k_zero_deg() {
    int i = blockIdx.x * blockDim.x + threadIdx.x;
    if (i < N_NODES) g_deg[i] = 0;
}

__global__ void k_hist(const void* __restrict__ ei) {
    int e = blockIdx.x * blockDim.x + threadIdx.x;
    if (e < N_EDGES) {
        int d = edge_at(ei, (long long)N_EDGES + e);
        if (d >= 0 && d < N_NODES) atomicAdd(&g_deg[d], 1);
    }
}

__global__ void k_scan1() {
    __shared__ int s[1024];
    int i = blockIdx.x * 1024 + threadIdx.x;
    int v = (i < N_NODES) ? g_deg[i] : 0;
    s[threadIdx.x] = v;
    __syncthreads();
    for (int off = 1; off < 1024; off <<= 1) {
        int t = (threadIdx.x >= off) ? s[threadIdx.x - off] : 0;
        __syncthreads();
        s[threadIdx.x] += t;
        __syncthreads();
    }
    if (i < N_NODES) g_rowptr[i] = s[threadIdx.x] - v;
    if (threadIdx.x == 1023) g_bsum[blockIdx.x] = s[1023];
}

__global__ void k_scan2(int nb) {
    __shared__ int s[64];
    int v = (threadIdx.x < nb) ? g_bsum[threadIdx.x] : 0;
    s[threadIdx.x] = v;
    __syncthreads();
    for (int off = 1; off < 64; off <<= 1) {
        int t = (threadIdx.x >= off) ? s[threadIdx.x - off] : 0;
        __syncthreads();
        s[threadIdx.x] += t;
        __syncthreads();
    }
    if (threadIdx.x < nb) g_bsum[threadIdx.x] = s[threadIdx.x] - v;
}

__global__ void k_scan3() {
    int i = blockIdx.x * blockDim.x + threadIdx.x;
    if (i < N_NODES) {
        int r = g_rowptr[i] + g_bsum[i >> 10];
        g_rowptr[i] = r;
        g_rowcur[i] = r;
        g_dis[i]    = rsqrtf((float)(g_deg[i] + 1));
    }
    if (i == 0) g_rowptr[N_NODES] = N_EDGES;
}

__global__ void k_scatter(const void* __restrict__ ei) {
    int e = blockIdx.x * blockDim.x + threadIdx.x;
    if (e < N_EDGES) {
        int s = edge_at(ei, e);
        int d = edge_at(ei, (long long)N_EDGES + e);
        if (d >= 0 && d < N_NODES && s >= 0 && s < N_NODES) {
            int p = atomicAdd(&g_rowcur[d], 1);
            g_colidx[p] = s;
        }
    }
}

// ---------------- feature scaling for layer-1 input (float4) ----------------
__global__ void k_scale16(const float4* __restrict__ x, float4* __restrict__ f) {
    int i = blockIdx.x * blockDim.x + threadIdx.x;   // over N*4 float4s
    if (i < N_NODES * 4) {
        float d = g_dis[i >> 2];
        float4 v = x[i];
        v.x *= d; v.y *= d; v.z *= d; v.w *= d;
        f[i] = v;
    }
}

// ---------------- aggregation kernels ---------------------------------------
// agg[n,:] = dis[n] * ( g[n,:] + sum_{e: dst=n} g[src[e],:] )

// D=16: half-warp per node
__global__ void k_agg16(const float* __restrict__ g, float* __restrict__ agg) {
    int t = blockIdx.x * blockDim.x + threadIdx.x;
    int node = t >> 4;
    if (node >= N_NODES) return;
    int lane = t & 15;

    float acc = __ldg(&g[node * 16 + lane]);
    int p   = g_rowptr[node];
    int end = g_rowptr[node + 1];
    for (; p + 4 <= end; p += 4) {
        int s0 = g_colidx[p + 0], s1 = g_colidx[p + 1];
        int s2 = g_colidx[p + 2], s3 = g_colidx[p + 3];
        acc += __ldg(&g[s0 * 16 + lane]);
        acc += __ldg(&g[s1 * 16 + lane]);
        acc += __ldg(&g[s2 * 16 + lane]);
        acc += __ldg(&g[s3 * 16 + lane]);
    }
    for (; p < end; p++)
        acc += __ldg(&g[g_colidx[p] * 16 + lane]);

    agg[node * 16 + lane] = acc * g_dis[node];
}

// D=32: warp per node, 1 float per lane
__global__ void k_agg32(const float* __restrict__ g, float* __restrict__ agg) {
    int warp = (blockIdx.x * blockDim.x + threadIdx.x) >> 5;
    if (warp >= N_NODES) return;
    int lane = threadIdx.x & 31;

    float acc = __ldg(&g[warp * 32 + lane]);
    int p   = g_rowptr[warp];
    int end = g_rowptr[warp + 1];
    for (; p + 4 <= end; p += 4) {
        int s0 = g_colidx[p + 0], s1 = g_colidx[p + 1];
        int s2 = g_colidx[p + 2], s3 = g_colidx[p + 3];
        acc += __ldg(&g[s0 * 32 + lane]);
        acc += __ldg(&g[s1 * 32 + lane]);
        acc += __ldg(&g[s2 * 32 + lane]);
        acc += __ldg(&g[s3 * 32 + lane]);
    }
    for (; p < end; p++)
        acc += __ldg(&g[g_colidx[p] * 32 + lane]);

    agg[warp * 32 + lane] = acc * g_dis[warp];
}

// D=64: warp per node, float2 per lane
__global__ void k_agg64(const float* __restrict__ g, float* __restrict__ agg) {
    int warp = (blockIdx.x * blockDim.x + threadIdx.x) >> 5;
    if (warp >= N_NODES) return;
    int lane = threadIdx.x & 31;

    const float2* g2 = (const float2*)g;
    float2 acc = __ldg(&g2[warp * 32 + lane]);
    int p   = g_rowptr[warp];
    int end = g_rowptr[warp + 1];
    for (; p + 4 <= end; p += 4) {
        int s0 = g_colidx[p + 0], s1 = g_colidx[p + 1];
        int s2 = g_colidx[p + 2], s3 = g_colidx[p + 3];
        float2 v0 = __ldg(&g2[s0 * 32 + lane]);
        float2 v1 = __ldg(&g2[s1 * 32 + lane]);
        float2 v2 = __ldg(&g2[s2 * 32 + lane]);
        float2 v3 = __ldg(&g2[s3 * 32 + lane]);
        acc.x += v0.x + v1.x + v2.x + v3.x;
        acc.y += v0.y + v1.y + v2.y + v3.y;
    }
    for (; p < end; p++) {
        float2 v = __ldg(&g2[g_colidx[p] * 32 + lane]);
        acc.x += v.x; acc.y += v.y;
    }

    float dd = g_dis[warp];
    float2 o; o.x = acc.x * dd; o.y = acc.y * dd;
    ((float2*)agg)[warp * 32 + lane] = o;
}

// ---------------- register-tiled GEMM + bias + relu (+dis) ------------------
// out[n,:] = relu(in[n,:] @ W + b) * (SCALE ? dis[n] : 1)
template <int DIN, int DOUT, bool SCALE>
__global__ void __launch_bounds__(256) k_gemm2(
        const float* __restrict__ in,
        const float* __restrict__ W,
        const float* __restrict__ b,
        float* __restrict__ out) {
    constexpr int NB  = 64;                         // nodes per block
    constexpr int TN  = (DOUT >= 32) ? 8 : 4;       // outputs per thread
    constexpr int TX  = DOUT / TN;                  // 2..16
    constexpr int TY  = 256 / TX;
    constexpr int TM  = NB / TY;                    // nodes per thread (1..4)
    constexpr int KC  = (DIN * DOUT >= 8192) ? 32 : DIN;
    constexpr int NKC = DIN / KC;
    constexpr int INP = KC + 1;                     // padded input row
    constexpr int SWW = DOUT + 2 * (DOUT / 32) + 2; // swizzled weight row

    static_assert(TM >= 1, "bad tiling");

    __shared__ float inS[NB * INP];
    __shared__ float Ws[KC * SWW];

    const int tid  = threadIdx.x;
    const int tx   = tid % TX;
    const int ty   = tid / TX;
    const int node0 = blockIdx.x * NB;

    // bias
    float bb[TN];
#pragma unroll
    for (int j = 0; j < TN; j++) bb[j] = __ldg(&b[tx * TN + j]);

    unsigned long long acc[TM][TN / 2];
#pragma unroll
    for (int m = 0; m < TM; m++)
#pragma unroll
        for (int j = 0; j < TN / 2; j++) acc[m][j] = 0ull;

    for (int kc = 0; kc < NKC; kc++) {
        const int k0 = kc * KC;
        // stage input tile
        for (int i = tid; i < NB * KC; i += 256) {
            int r = i / KC, c = i - r * KC;
            int node = node0 + r;
            inS[r * INP + c] =
                (node < N_NODES) ? __ldg(&in[(size_t)node * DIN + k0 + c]) : 0.f;
        }
        // stage weight tile (swizzled to kill tx bank conflicts)
        for (int i = tid; i < KC * DOUT; i += 256) {
            int r = i / DOUT, c = i - r * DOUT;
            Ws[r * SWW + c + 2 * (c >> 5)] = __ldg(&W[(size_t)(k0 + r) * DOUT + c]);
        }
        __syncthreads();

#pragma unroll
        for (int k = 0; k < KC; k++) {
            unsigned long long a2[TM];
#pragma unroll
            for (int m = 0; m < TM; m++) {
                float a = inS[(ty * TM + m) * INP + k];
                a2[m] = pack2(a, a);
            }
#pragma unroll
            for (int j = 0; j < TN / 2; j++) {
                int c = tx * TN + 2 * j;
                float2 wv = *reinterpret_cast<const float2*>(
                    &Ws[k * SWW + c + 2 * (c >> 5)]);
                unsigned long long w2 = pack2(wv.x, wv.y);
#pragma unroll
                for (int m = 0; m < TM; m++)
                    acc[m][j] = fma2(a2[m], w2, acc[m][j]);
            }
        }
        if (kc + 1 < NKC) __syncthreads();
    }

    // epilogue
#pragma unroll
    for (int m = 0; m < TM; m++) {
        int node = node0 + ty * TM + m;
        if (node >= N_NODES) continue;
        float sc = SCALE ? g_dis[node] : 1.f;
        float vals[TN];
#pragma unroll
        for (int j = 0; j < TN / 2; j++) {
            float v0, v1;
            unpack2(acc[m][j], v0, v1);
            v0 += bb[2 * j];     v1 += bb[2 * j + 1];
            v0 = v0 > 0.f ? v0 : 0.f;
            v1 = v1 > 0.f ? v1 : 0.f;
            vals[2 * j]     = v0 * sc;
            vals[2 * j + 1] = v1 * sc;
        }
        float4* o = (float4*)(out + (size_t)node * DOUT + tx * TN);
#pragma unroll
        for (int q = 0; q < TN / 4; q++)
            o[q] = make_float4(vals[4 * q], vals[4 * q + 1],
                               vals[4 * q + 2], vals[4 * q + 3]);
    }
}

// ---------------- launch ------------------------------------------------------
extern "C" void kernel_launch(void* const* d_in, const int* in_sizes, int n_in,
                              void* d_out, int out_size) {
    const float* x  = (const float*)d_in[0];
    const void*  ei = d_in[1];
    const float *W1 = (const float*)d_in[2],  *b1 = (const float*)d_in[3];
    const float *W2 = (const float*)d_in[4],  *b2 = (const float*)d_in[5];
    const float *W3 = (const float*)d_in[6],  *b3 = (const float*)d_in[7];
    const float *Wl1= (const float*)d_in[8],  *bl1= (const float*)d_in[9];
    const float *Wl2= (const float*)d_in[10], *bl2= (const float*)d_in[11];
    const float *Wl3= (const float*)d_in[12], *bl3= (const float*)d_in[13];
    float* out = (float*)d_out;

    float *feat, *agg, *actA, *actB;
    cudaGetSymbolAddress((void**)&feat, g_feat);
    cudaGetSymbolAddress((void**)&agg,  g_agg);
    cudaGetSymbolAddress((void**)&actA, g_actA);
    cudaGetSymbolAddress((void**)&actB, g_actB);

    const int TB = 256;
    const int nodeBlocks = (N_NODES + TB - 1) / TB;
    const int edgeBlocks = (N_EDGES + TB - 1) / TB;
    const int scanBlocks = (N_NODES + 1023) / 1024;
    const int gemmBlocks = (N_NODES + 63) / 64;           // 782
    const int hwBlocks   = (N_NODES * 16 + TB - 1) / TB;  // half-warp per node
    const int wBlocks    = (N_NODES * 32 + TB - 1) / TB;  // warp per node

    // --- graph structure ---
    k_detect<<<1, 32>>>(ei);
    k_zero_deg<<<nodeBlocks, TB>>>();
    k_hist<<<edgeBlocks, TB>>>(ei);
    k_scan1<<<scanBlocks, 1024>>>();
    k_scan2<<<1, 64>>>(scanBlocks);
    k_scan3<<<nodeBlocks, TB>>>();
    k_scatter<<<edgeBlocks, TB>>>(ei);

    // --- conv 1: 16 -> 32 ---
    k_scale16<<<(N_NODES * 4 + TB - 1) / TB, TB>>>((const float4*)x, (float4*)feat);
    k_agg16<<<hwBlocks, TB>>>(feat, agg);
    k_gemm2<16, 32, true><<<gemmBlocks, TB>>>(agg, W1, b1, feat);

    // --- conv 2: 32 -> 64 ---
    k_agg32<<<wBlocks, TB>>>(feat, agg);
    k_gemm2<32, 64, true><<<gemmBlocks, TB>>>(agg, W2, b2, feat);

    // --- conv 3: 64 -> 128 ---
    k_agg64<<<wBlocks, TB>>>(feat, agg);
    k_gemm2<64, 128, false><<<gemmBlocks, TB>>>(agg, W3, b3, actA);

    // --- dense layers ---
    k_gemm2<128, 64, false><<<gemmBlocks, TB>>>(actA, Wl1, bl1, actB);
    k_gemm2<64, 32, false><<<gemmBlocks, TB>>>(actB, Wl2, bl2, actA);
    k_gemm2<32, 16, false><<<gemmBlocks, TB>>>(actA, Wl3, bl3, out);
}